// round 1
// baseline (speedup 1.0000x reference)
#include <cuda_runtime.h>
#include <cstdint>

// ---------------------------------------------------------------------------
// Problem constants (fixed shapes from reference)
// ---------------------------------------------------------------------------
namespace {
constexpr int T_STEPS = 128;
constexpr int BATCH   = 512;
constexpr int HID     = 512;
constexpr int INP     = 512;
constexpr int M_TOT   = T_STEPS * BATCH;          // 65536 GEMM rows
constexpr long long BH = (long long)BATCH * HID;  // 262144 independent sequences
}

// Scratch for projected input xp = x @ W^T + b  : [T*B, H] fp32 (128 MB, static)
__device__ float g_xp[(size_t)M_TOT * HID];

// ---------------------------------------------------------------------------
// SGEMM: C[m,n] = sum_k A[m,k] * W[n,k] + bias[n]
// A: [M, K] row-major (x flattened over T,B), W: [N, K] row-major.
// 128x128 block tile, BK=16, 256 threads, 8x8 per-thread microtile.
// ---------------------------------------------------------------------------
namespace {
constexpr int BM = 128, BN = 128, BK = 16, TM = 8, TN = 8;
}

__global__ __launch_bounds__(256)
void sgemm_bias_kernel(const float* __restrict__ A,
                       const float* __restrict__ W,
                       const float* __restrict__ bias)
{
    __shared__ float As[BK][BM + 4];   // +4 pad keeps float4 alignment (132*4=528B, 16B-mult)
    __shared__ float Bs[BK][BN + 4];

    const int tid = threadIdx.x;
    const int m0  = blockIdx.y * BM;
    const int n0  = blockIdx.x * BN;

    const int tx = tid & 15;           // 16 cols of threads
    const int ty = tid >> 4;           // 16 rows of threads
    const int rowBase = ty * TM;
    const int colBase = tx * TN;

    float acc[TM][TN];
    #pragma unroll
    for (int i = 0; i < TM; ++i)
        #pragma unroll
        for (int j = 0; j < TN; ++j) acc[i][j] = 0.0f;

    for (int kt = 0; kt < INP; kt += BK) {
        // Load 128x16 A-tile and 128x16 W-tile, transposed into smem.
        // 512 float4 per tile / 256 threads = 2 per thread.
        #pragma unroll
        for (int i = 0; i < 2; ++i) {
            const int f4  = tid + i * 256;
            const int r   = f4 >> 2;
            const int c4  = (f4 & 3) * 4;
            float4 av = *(const float4*)(A + (size_t)(m0 + r) * INP + kt + c4);
            As[c4 + 0][r] = av.x; As[c4 + 1][r] = av.y;
            As[c4 + 2][r] = av.z; As[c4 + 3][r] = av.w;
            float4 bv = *(const float4*)(W + (size_t)(n0 + r) * INP + kt + c4);
            Bs[c4 + 0][r] = bv.x; Bs[c4 + 1][r] = bv.y;
            Bs[c4 + 2][r] = bv.z; Bs[c4 + 3][r] = bv.w;
        }
        __syncthreads();

        #pragma unroll
        for (int k = 0; k < BK; ++k) {
            float a_reg[TM], b_reg[TN];
            *(float4*)&a_reg[0] = *(const float4*)&As[k][rowBase];
            *(float4*)&a_reg[4] = *(const float4*)&As[k][rowBase + 4];
            *(float4*)&b_reg[0] = *(const float4*)&Bs[k][colBase];
            *(float4*)&b_reg[4] = *(const float4*)&Bs[k][colBase + 4];
            #pragma unroll
            for (int i = 0; i < TM; ++i)
                #pragma unroll
                for (int j = 0; j < TN; ++j)
                    acc[i][j] = fmaf(a_reg[i], b_reg[j], acc[i][j]);
        }
        __syncthreads();
    }

    // Epilogue: add bias, store to scratch.
    float bia[TN];
    #pragma unroll
    for (int j = 0; j < TN; ++j) bia[j] = bias[n0 + colBase + j];

    #pragma unroll
    for (int i = 0; i < TM; ++i) {
        float* crow = g_xp + (size_t)(m0 + rowBase + i) * HID + n0 + colBase;
        float4 o0, o1;
        o0.x = acc[i][0] + bia[0]; o0.y = acc[i][1] + bia[1];
        o0.z = acc[i][2] + bia[2]; o0.w = acc[i][3] + bia[3];
        o1.x = acc[i][4] + bia[4]; o1.y = acc[i][5] + bia[5];
        o1.z = acc[i][6] + bia[6]; o1.w = acc[i][7] + bia[7];
        *(float4*)(crow)     = o0;
        *(float4*)(crow + 4) = o1;
    }
}

// ---------------------------------------------------------------------------
// Recurrent LIF scan: one thread per (b,h) element; loops over T.
// Arithmetic mirrors the reference exactly:
//   v = v + (y - v) * 0.5f          (decay_input charge, tau=2)
//   s = (v >= 1.0f)                 (heaviside on v - vth)
//   v = v - s                       (soft reset, vth=1)
//   avg over 4 substeps via acc * 0.25f  (exact scaling)
// Layer i's input is layer i-1's avg_v at the same t (layer 0: xp[t]).
// out[t] = avg spikes of layer 3; states[l] = avg_v of layer l at t = T-1.
// ---------------------------------------------------------------------------
__global__ __launch_bounds__(256)
void lif_scan_kernel(float* __restrict__ out, float* __restrict__ states)
{
    const long long idx = (long long)blockIdx.x * blockDim.x + threadIdx.x;

    float v[4]  = {0.f, 0.f, 0.f, 0.f};
    float av[4] = {0.f, 0.f, 0.f, 0.f};

    const float* px = g_xp + idx;
    float*       po = out  + idx;

    for (int t = 0; t < T_STEPS; ++t) {
        float y  = px[(size_t)t * BH];
        float sc = 0.f;
        #pragma unroll
        for (int l = 0; l < 4; ++l) {
            float vv   = v[l];
            float accv = 0.f;
            float accs = 0.f;
            #pragma unroll
            for (int s = 0; s < 4; ++s) {
                vv = vv + (y - vv) * 0.5f;            // charge
                float sp = (vv >= 1.0f) ? 1.0f : 0.0f; // fire
                vv = vv - sp;                          // soft reset
                accv += vv;
                accs += sp;
            }
            v[l]  = vv;
            y     = accv * 0.25f;   // avg_v -> next layer's input
            av[l] = y;
            sc    = accs * 0.25f;   // only last layer's survives (DCE for l<3)
        }
        po[(size_t)t * BH] = sc;
    }

    #pragma unroll
    for (int l = 0; l < 4; ++l)
        states[(size_t)l * BH + idx] = av[l];
}

// ---------------------------------------------------------------------------
// Launch
// ---------------------------------------------------------------------------
extern "C" void kernel_launch(void* const* d_in, const int* in_sizes, int n_in,
                              void* d_out, int out_size)
{
    const float* x  = (const float*)d_in[0];   // [T, B, INP]
    const float* W  = (const float*)d_in[1];   // [HID, INP]
    const float* b  = (const float*)d_in[2];   // [HID]

    float* out    = (float*)d_out;                       // [T, B, H]
    float* states = out + (size_t)T_STEPS * BH;          // [4, B, H]

    dim3 gemm_grid(HID / BN, M_TOT / BM);                // (4, 512)
    sgemm_bias_kernel<<<gemm_grid, 256>>>(x, W, b);

    lif_scan_kernel<<<(unsigned)(BH / 256), 256>>>(out, states);
}

// round 3
// speedup vs baseline: 1.1244x; 1.1244x over previous
#include <cuda_runtime.h>
#include <cuda_bf16.h>
#include <cstdint>

// ---------------------------------------------------------------------------
// Problem constants
// ---------------------------------------------------------------------------
namespace {
constexpr int T_STEPS = 128, BATCH = 512, HID = 512, INP = 512;
constexpr int M_TOT = T_STEPS * BATCH;              // 65536 GEMM rows
constexpr long long BH = (long long)BATCH * HID;    // 262144 sequences

// GEMM tiling
constexpr int BM = 128, BN = 128, BK = 16;
constexpr int CHUNKS = INP / BK;                    // 32
// smem tile: 128 rows x 48B pitch (16 bf16 used + pad for ldmatrix banks)
constexpr int PITCH   = 48;
constexpr int TILE_B  = 128 * PITCH;                // 6144 bytes per split
constexpr int A_OFF   = 0;                          // 3 A splits
constexpr int B_OFF   = 3 * TILE_B;                 // 3 B splits
constexpr int STAGE_B = 6 * TILE_B;                 // 36864 per stage
constexpr int SMEM_TOTAL = 2 * STAGE_B;             // 73728
}

// Scratch for projected input xp = x @ W^T + b : [T*B, H] fp32
__device__ float g_xp[(size_t)M_TOT * HID];

// ---------------------------------------------------------------------------
// PTX helpers
// ---------------------------------------------------------------------------
__device__ __forceinline__ uint32_t smem_u32(const void* p) {
    uint32_t a;
    asm("{ .reg .u64 t; cvta.to.shared.u64 t, %1; cvt.u32.u64 %0, t; }"
        : "=r"(a) : "l"(p));
    return a;
}
__device__ __forceinline__ void ldsm_x4(uint32_t* r, uint32_t addr) {
    asm volatile("ldmatrix.sync.aligned.m8n8.x4.shared.b16 {%0,%1,%2,%3}, [%4];"
                 : "=r"(r[0]), "=r"(r[1]), "=r"(r[2]), "=r"(r[3]) : "r"(addr));
}
__device__ __forceinline__ void mma_bf16(float* c, const uint32_t* a,
                                         const uint32_t* b) {
    asm volatile(
        "mma.sync.aligned.m16n8k16.row.col.f32.bf16.bf16.f32 "
        "{%0,%1,%2,%3}, {%4,%5,%6,%7}, {%8,%9}, {%0,%1,%2,%3};"
        : "+f"(c[0]), "+f"(c[1]), "+f"(c[2]), "+f"(c[3])
        : "r"(a[0]), "r"(a[1]), "r"(a[2]), "r"(a[3]), "r"(b[0]), "r"(b[1]));
}
__device__ __forceinline__ uint32_t bpack(__nv_bfloat16 a, __nv_bfloat16 b) {
    __nv_bfloat162 t(a, b);
    return *reinterpret_cast<uint32_t*>(&t);
}

// ---------------------------------------------------------------------------
// Tensor-core (HMMA) GEMM: C[m,n] = sum_k A[m,k]*W[n,k] + bias[n] -> g_xp
// fp32 via 3-word bf16 split, 6 MMA terms: hh + hm + mh + hl + lh + mm
// ---------------------------------------------------------------------------
__global__ __launch_bounds__(256, 1)
void gemm_hmma_kernel(const float* __restrict__ A,
                      const float* __restrict__ W,
                      const float* __restrict__ bias)
{
    extern __shared__ char smem[];
    const uint32_t sbase = smem_u32(smem);
    const int tid = threadIdx.x;
    const int wid = tid >> 5;
    const int lid = tid & 31;
    const int n0 = blockIdx.x * BN;
    const int m0 = blockIdx.y * BM;

    const int warp_m = wid & 1;         // 0..1 -> 64-row half
    const int warp_n = wid >> 1;        // 0..3 -> 32-col slice

    // gmem staging coords: f4 = tid + i*256 (i=0,1); row=f4>>2, c4=f4&3
    const int r0 = tid >> 2,      c0 = (tid & 3);
    const int r1 = (tid + 256) >> 2, c1 = ((tid + 256) & 3);

    // ldmatrix per-lane offsets
    const int quad = lid >> 3, lrow = lid & 7;
    // A: quads = (rows0-7,k0)(rows8-15,k0)(rows0-7,k8)(rows8-15,k8)
    const uint32_t laneA = (uint32_t)(((quad & 1) * 8 + lrow) * PITCH + (quad >> 1) * 16);
    // B: quads = (tile0,k0)(tile0,k8)(tile1,k0)(tile1,k8)
    const uint32_t laneB = (uint32_t)(((quad >> 1) * 8 + lrow) * PITCH + (quad & 1) * 16);

    float acc[4][4][4];
    #pragma unroll
    for (int i = 0; i < 4; ++i)
        #pragma unroll
        for (int j = 0; j < 4; ++j)
            #pragma unroll
            for (int k = 0; k < 4; ++k) acc[i][j][k] = 0.f;

    float4 avr[2], bvr[2];

    auto load_chunk = [&](int c) {
        const int kt = c * BK;
        avr[0] = *(const float4*)(A + (size_t)(m0 + r0) * INP + kt + c0 * 4);
        avr[1] = *(const float4*)(A + (size_t)(m0 + r1) * INP + kt + c1 * 4);
        bvr[0] = *(const float4*)(W + (size_t)(n0 + r0) * INP + kt + c0 * 4);
        bvr[1] = *(const float4*)(W + (size_t)(n0 + r1) * INP + kt + c1 * 4);
    };

    auto split_store = [&](int stage) {
        char* sb = smem + stage * STAGE_B;
        const int rr[2] = {r0, r1};
        const int cc[2] = {c0, c1};
        #pragma unroll
        for (int half = 0; half < 2; ++half) {   // 0: A, 1: B(=W)
            char* base = sb + (half ? B_OFF : A_OFF);
            #pragma unroll
            for (int i = 0; i < 2; ++i) {
                const float4 v = half ? bvr[i] : avr[i];
                const float f[4] = {v.x, v.y, v.z, v.w};
                __nv_bfloat16 hb[4], mb[4], lb[4];
                #pragma unroll
                for (int j = 0; j < 4; ++j) {
                    hb[j] = __float2bfloat16(f[j]);
                    const float e1 = f[j] - __bfloat162float(hb[j]);
                    mb[j] = __float2bfloat16(e1);
                    const float e2 = e1 - __bfloat162float(mb[j]);
                    lb[j] = __float2bfloat16(e2);
                }
                const uint32_t off = (uint32_t)(rr[i] * PITCH + cc[i] * 8);
                *(uint2*)(base + 0 * TILE_B + off) = make_uint2(bpack(hb[0], hb[1]), bpack(hb[2], hb[3]));
                *(uint2*)(base + 1 * TILE_B + off) = make_uint2(bpack(mb[0], mb[1]), bpack(mb[2], mb[3]));
                *(uint2*)(base + 2 * TILE_B + off) = make_uint2(bpack(lb[0], lb[1]), bpack(lb[2], lb[3]));
            }
        }
    };

    // ---- prologue ----
    load_chunk(0);
    split_store(0);
    load_chunk(1);
    __syncthreads();

    // split pairs: hh, hm, mh, hl, lh, mm
    const int pa[6] = {0, 0, 1, 0, 2, 1};
    const int pb[6] = {0, 1, 0, 2, 0, 1};

    for (int c = 0; c < CHUNKS; ++c) {
        const int p = c & 1;

        if (c + 1 < CHUNKS) split_store(1 - p);   // regs hold chunk c+1

        // fragment loads for all 3 splits
        const uint32_t aBase = sbase + p * STAGE_B + A_OFF +
                               (uint32_t)(warp_m * 64 * PITCH) + laneA;
        const uint32_t bBase = sbase + p * STAGE_B + B_OFF +
                               (uint32_t)(warp_n * 32 * PITCH) + laneB;
        uint32_t af[3][4][4];   // [split][mtile][reg]
        uint32_t bf[3][4][2];   // [split][ntile][reg]
        #pragma unroll
        for (int s = 0; s < 3; ++s) {
            #pragma unroll
            for (int mt = 0; mt < 4; ++mt)
                ldsm_x4(af[s][mt], aBase + (uint32_t)(s * TILE_B + mt * 16 * PITCH));
            #pragma unroll
            for (int bp = 0; bp < 2; ++bp) {
                uint32_t r4[4];
                ldsm_x4(r4, bBase + (uint32_t)(s * TILE_B + bp * 16 * PITCH));
                bf[s][bp * 2 + 0][0] = r4[0]; bf[s][bp * 2 + 0][1] = r4[1];
                bf[s][bp * 2 + 1][0] = r4[2]; bf[s][bp * 2 + 1][1] = r4[3];
            }
        }

        #pragma unroll
        for (int pr = 0; pr < 6; ++pr) {
            const int sa = pa[pr], sb2 = pb[pr];
            #pragma unroll
            for (int mt = 0; mt < 4; ++mt)
                #pragma unroll
                for (int nt = 0; nt < 4; ++nt)
                    mma_bf16(acc[mt][nt], af[sa][mt], bf[sb2][nt]);
        }

        if (c + 2 < CHUNKS) load_chunk(c + 2);
        __syncthreads();
    }

    // ---- epilogue: +bias, store fp32 to g_xp ----
    const int tr = lid >> 2;            // 0..7
    const int tc = (lid & 3) * 2;       // 0,2,4,6
    #pragma unroll
    for (int nt = 0; nt < 4; ++nt) {
        const int col = n0 + warp_n * 32 + nt * 8 + tc;
        const float2 bb = *(const float2*)(bias + col);
        #pragma unroll
        for (int mt = 0; mt < 4; ++mt) {
            const int row = m0 + warp_m * 64 + mt * 16 + tr;
            float2 o0, o1;
            o0.x = acc[mt][nt][0] + bb.x; o0.y = acc[mt][nt][1] + bb.y;
            o1.x = acc[mt][nt][2] + bb.x; o1.y = acc[mt][nt][3] + bb.y;
            *(float2*)(g_xp + (size_t)row * HID + col)       = o0;
            *(float2*)(g_xp + (size_t)(row + 8) * HID + col) = o1;
        }
    }
}

// ---------------------------------------------------------------------------
// Recurrent LIF scan: one thread per (b,h), loops over T. Exact reference math.
// ---------------------------------------------------------------------------
__global__ __launch_bounds__(256)
void lif_scan_kernel(float* __restrict__ out, float* __restrict__ states)
{
    const long long idx = (long long)blockIdx.x * blockDim.x + threadIdx.x;

    float v[4]  = {0.f, 0.f, 0.f, 0.f};
    float av[4] = {0.f, 0.f, 0.f, 0.f};

    const float* px = g_xp + idx;
    float*       po = out  + idx;

    for (int t = 0; t < T_STEPS; ++t) {
        float y  = px[(size_t)t * BH];
        float sc = 0.f;
        #pragma unroll
        for (int l = 0; l < 4; ++l) {
            float vv   = v[l];
            float accv = 0.f;
            float accs = 0.f;
            #pragma unroll
            for (int s = 0; s < 4; ++s) {
                vv = vv + (y - vv) * 0.5f;             // charge
                float sp = (vv >= 1.0f) ? 1.0f : 0.0f; // fire
                vv = vv - sp;                           // soft reset
                accv += vv;
                accs += sp;
            }
            v[l]  = vv;
            y     = accv * 0.25f;
            av[l] = y;
            sc    = accs * 0.25f;
        }
        po[(size_t)t * BH] = sc;
    }

    #pragma unroll
    for (int l = 0; l < 4; ++l)
        states[(size_t)l * BH + idx] = av[l];
}

// ---------------------------------------------------------------------------
// Launch
// ---------------------------------------------------------------------------
extern "C" void kernel_launch(void* const* d_in, const int* in_sizes, int n_in,
                              void* d_out, int out_size)
{
    const float* x = (const float*)d_in[0];   // [T, B, INP]
    const float* W = (const float*)d_in[1];   // [HID, INP]
    const float* b = (const float*)d_in[2];   // [HID]

    float* out    = (float*)d_out;                    // [T, B, H]
    float* states = out + (size_t)T_STEPS * BH;       // [4, B, H]

    cudaFuncSetAttribute(gemm_hmma_kernel,
                         cudaFuncAttributeMaxDynamicSharedMemorySize, SMEM_TOTAL);

    dim3 gemm_grid(HID / BN, M_TOT / BM);             // (4, 512)
    gemm_hmma_kernel<<<gemm_grid, 256, SMEM_TOTAL>>>(x, W, b);

    lif_scan_kernel<<<(unsigned)(BH / 256), 256>>>(out, states);
}

// round 4
// speedup vs baseline: 1.2447x; 1.1070x over previous
#include <cuda_runtime.h>
#include <cuda_bf16.h>
#include <cstdint>

// ---------------------------------------------------------------------------
// Problem constants
// ---------------------------------------------------------------------------
namespace {
constexpr int T_STEPS = 128, BATCH = 512, HID = 512, INP = 512;
constexpr int M_TOT = T_STEPS * BATCH;              // 65536 GEMM rows
constexpr long long BH = (long long)BATCH * HID;    // 262144 sequences

// GEMM tiling
constexpr int BM = 128, BN = 128, BK = 32;
constexpr int CHUNKS = INP / BK;                    // 16
constexpr int PITCH  = 80;                          // 64B data + 16B pad (bank-clean)
constexpr int TILE_B = 128 * PITCH;                 // 10240 B per operand tile
constexpr int STAGE_B = 4 * TILE_B;                 // Ah, Am, Bh, Bm = 40960
constexpr int NSTAGE = 4;
constexpr int SMEM_TOTAL = NSTAGE * STAGE_B;        // 163840
}

// Static scratch (allowed; no allocs)
__device__ float         g_xp[(size_t)M_TOT * HID];     // xp fp32, 128 MB
__device__ __nv_bfloat16 g_xh[(size_t)M_TOT * INP];     // x hi split, 64 MB
__device__ __nv_bfloat16 g_xm[(size_t)M_TOT * INP];     // x mid split, 64 MB
__device__ __nv_bfloat16 g_wh[(size_t)HID * INP];
__device__ __nv_bfloat16 g_wm[(size_t)HID * INP];

// ---------------------------------------------------------------------------
// PTX helpers
// ---------------------------------------------------------------------------
__device__ __forceinline__ uint32_t smem_u32(const void* p) {
    uint32_t a;
    asm("{ .reg .u64 t; cvta.to.shared.u64 t, %1; cvt.u32.u64 %0, t; }"
        : "=r"(a) : "l"(p));
    return a;
}
__device__ __forceinline__ void ldsm_x4(uint32_t* r, uint32_t addr) {
    asm volatile("ldmatrix.sync.aligned.m8n8.x4.shared.b16 {%0,%1,%2,%3}, [%4];"
                 : "=r"(r[0]), "=r"(r[1]), "=r"(r[2]), "=r"(r[3]) : "r"(addr));
}
__device__ __forceinline__ void mma_bf16(float* c, const uint32_t* a,
                                         const uint32_t* b) {
    asm volatile(
        "mma.sync.aligned.m16n8k16.row.col.f32.bf16.bf16.f32 "
        "{%0,%1,%2,%3}, {%4,%5,%6,%7}, {%8,%9}, {%0,%1,%2,%3};"
        : "+f"(c[0]), "+f"(c[1]), "+f"(c[2]), "+f"(c[3])
        : "r"(a[0]), "r"(a[1]), "r"(a[2]), "r"(a[3]), "r"(b[0]), "r"(b[1]));
}
__device__ __forceinline__ void cp16(uint32_t dst, const void* src) {
    asm volatile("cp.async.cg.shared.global [%0], [%1], 16;"
                 :: "r"(dst), "l"(src) : "memory");
}
__device__ __forceinline__ void cp_commit() {
    asm volatile("cp.async.commit_group;" ::: "memory");
}
__device__ __forceinline__ void cp_wait2() {
    asm volatile("cp.async.wait_group 2;" ::: "memory");
}
__device__ __forceinline__ uint32_t bpack(__nv_bfloat16 a, __nv_bfloat16 b) {
    __nv_bfloat162 t(a, b);
    return *reinterpret_cast<uint32_t*>(&t);
}

// ---------------------------------------------------------------------------
// Split pass: fp32 -> (hi, mid) bf16.  is_w selects destination arrays.
// ---------------------------------------------------------------------------
__global__ __launch_bounds__(256)
void split_kernel(const float4* __restrict__ src, int n4, int is_w)
{
    const int i = blockIdx.x * blockDim.x + threadIdx.x;
    if (i >= n4) return;
    const float4 v = src[i];
    const float f[4] = {v.x, v.y, v.z, v.w};
    __nv_bfloat16 h[4], m[4];
    #pragma unroll
    for (int j = 0; j < 4; ++j) {
        h[j] = __float2bfloat16(f[j]);
        m[j] = __float2bfloat16(f[j] - __bfloat162float(h[j]));
    }
    uint2* hd = (uint2*)(is_w ? g_wh : g_xh);
    uint2* md = (uint2*)(is_w ? g_wm : g_xm);
    hd[i] = make_uint2(bpack(h[0], h[1]), bpack(h[2], h[3]));
    md[i] = make_uint2(bpack(m[0], m[1]), bpack(m[2], m[3]));
}

// ---------------------------------------------------------------------------
// HMMA GEMM: g_xp[m,n] = sum_k x[m,k]*W[n,k] + bias[n]
// fp32 via 2-word bf16 split, 3 terms: hh + hm + mh
// cp.async 4-stage pipeline, BK=32 chunks.
// ---------------------------------------------------------------------------
__global__ __launch_bounds__(256, 1)
void gemm_hmma_kernel(const float* __restrict__ bias)
{
    extern __shared__ char smem[];
    const uint32_t sbase = smem_u32(smem);
    const int tid = threadIdx.x;
    const int wid = tid >> 5;
    const int lid = tid & 31;
    const int n0 = blockIdx.x * BN;
    const int m0 = blockIdx.y * BM;

    const int warp_m = wid & 1;          // 64-row half
    const int warp_n = wid >> 1;         // 32-col slice

    // ldmatrix lane addressing (pitch 80B, conflict-free)
    const int quad = lid >> 3, lrow = lid & 7;
    const uint32_t laneA = (uint32_t)(((quad & 1) * 8 + lrow) * PITCH + (quad >> 1) * 16);
    const uint32_t laneB = (uint32_t)(((quad >> 1) * 8 + lrow) * PITCH + (quad & 1) * 16);

    float acc[4][4][4];
    #pragma unroll
    for (int i = 0; i < 4; ++i)
        #pragma unroll
        for (int j = 0; j < 4; ++j)
            #pragma unroll
            for (int k = 0; k < 4; ++k) acc[i][j][k] = 0.f;

    // stage fill: 2048 x 16B chunks, 8 per thread; tiles {xh, xm, wh, wm}
    auto issue_stage = [&](int c) {
        const int kt = c * BK;
        const uint32_t sdst = sbase + (uint32_t)((c & 3) * STAGE_B);
        #pragma unroll
        for (int i = 0; i < 8; ++i) {
            const int q    = i * 256 + tid;
            const int tile = q >> 9;           // compile-time per i
            const int t    = q & 511;
            const int row  = t >> 2;
            const int cc   = t & 3;
            const __nv_bfloat16* src;
            if      (tile == 0) src = g_xh + (size_t)(m0 + row) * INP + kt + cc * 8;
            else if (tile == 1) src = g_xm + (size_t)(m0 + row) * INP + kt + cc * 8;
            else if (tile == 2) src = g_wh + (size_t)(n0 + row) * INP + kt + cc * 8;
            else                src = g_wm + (size_t)(n0 + row) * INP + kt + cc * 8;
            cp16(sdst + (uint32_t)(tile * TILE_B + row * PITCH + cc * 16), src);
        }
        cp_commit();
    };

    issue_stage(0);
    issue_stage(1);
    issue_stage(2);

    for (int c = 0; c < CHUNKS; ++c) {
        cp_wait2();
        __syncthreads();

        const uint32_t stg = sbase + (uint32_t)((c & 3) * STAGE_B);
        const uint32_t aB  = stg + (uint32_t)(warp_m * 64 * PITCH) + laneA;
        const uint32_t bB  = stg + (uint32_t)(2 * TILE_B + warp_n * 32 * PITCH) + laneB;

        #pragma unroll
        for (int ks = 0; ks < 2; ++ks) {               // two K=16 sub-steps
            uint32_t af[2][4][4];                       // [split][mtile][reg]
            uint32_t bf[2][4][2];                       // [split][ntile][reg]
            #pragma unroll
            for (int s = 0; s < 2; ++s) {
                #pragma unroll
                for (int mt = 0; mt < 4; ++mt)
                    ldsm_x4(af[s][mt],
                            aB + (uint32_t)(s * TILE_B + mt * 16 * PITCH + ks * 32));
                #pragma unroll
                for (int bp = 0; bp < 2; ++bp) {
                    uint32_t r4[4];
                    ldsm_x4(r4, bB + (uint32_t)(s * TILE_B + bp * 16 * PITCH + ks * 32));
                    bf[s][bp * 2 + 0][0] = r4[0]; bf[s][bp * 2 + 0][1] = r4[1];
                    bf[s][bp * 2 + 1][0] = r4[2]; bf[s][bp * 2 + 1][1] = r4[3];
                }
            }
            // terms: hh, hm, mh
            const int pa[3] = {0, 0, 1};
            const int pb[3] = {0, 1, 0};
            #pragma unroll
            for (int pr = 0; pr < 3; ++pr) {
                #pragma unroll
                for (int mt = 0; mt < 4; ++mt)
                    #pragma unroll
                    for (int nt = 0; nt < 4; ++nt)
                        mma_bf16(acc[mt][nt], af[pa[pr]][mt], bf[pb[pr]][nt]);
            }
        }

        if (c + 3 < CHUNKS) issue_stage(c + 3);
        else                cp_commit();    // empty group keeps wait arithmetic exact
    }

    // ---- epilogue: +bias, store fp32 ----
    const int tr = lid >> 2;
    const int tc = (lid & 3) * 2;
    #pragma unroll
    for (int nt = 0; nt < 4; ++nt) {
        const int col = n0 + warp_n * 32 + nt * 8 + tc;
        const float2 bb = *(const float2*)(bias + col);
        #pragma unroll
        for (int mt = 0; mt < 4; ++mt) {
            const int row = m0 + warp_m * 64 + mt * 16 + tr;
            float2 o0, o1;
            o0.x = acc[mt][nt][0] + bb.x; o0.y = acc[mt][nt][1] + bb.y;
            o1.x = acc[mt][nt][2] + bb.x; o1.y = acc[mt][nt][3] + bb.y;
            *(float2*)(g_xp + (size_t)row * HID + col)       = o0;
            *(float2*)(g_xp + (size_t)(row + 8) * HID + col) = o1;
        }
    }
}

// ---------------------------------------------------------------------------
// Recurrent LIF scan: 2 elems/thread (float2) + next-t prefetch.
// Per-element arithmetic identical to the reference.
// ---------------------------------------------------------------------------
__global__ __launch_bounds__(256)
void lif_scan_kernel(float* __restrict__ out, float* __restrict__ states)
{
    const long long i2 = (long long)blockIdx.x * blockDim.x + threadIdx.x; // 0..BH/2-1
    const long long STRIDE2 = BH / 2;

    const float2* px = (const float2*)g_xp + i2;
    float2*       po = (float2*)out + i2;

    float v[4][2], av[4][2];
    #pragma unroll
    for (int l = 0; l < 4; ++l) { v[l][0] = v[l][1] = 0.f; av[l][0] = av[l][1] = 0.f; }

    float2 ycur = px[0];
    for (int t = 0; t < T_STEPS; ++t) {
        const float2 ynext = (t + 1 < T_STEPS) ? px[(size_t)(t + 1) * STRIDE2]
                                               : make_float2(0.f, 0.f);
        float y[2]  = {ycur.x, ycur.y};
        float sc[2] = {0.f, 0.f};
        #pragma unroll
        for (int l = 0; l < 4; ++l) {
            #pragma unroll
            for (int e = 0; e < 2; ++e) {
                float vv   = v[l][e];
                float accv = 0.f, accs = 0.f;
                #pragma unroll
                for (int s = 0; s < 4; ++s) {
                    vv = vv + (y[e] - vv) * 0.5f;              // charge
                    const float sp = (vv >= 1.0f) ? 1.0f : 0.0f; // fire
                    vv = vv - sp;                               // soft reset
                    accv += vv;
                    accs += sp;
                }
                v[l][e]  = vv;
                y[e]     = accv * 0.25f;
                av[l][e] = y[e];
                sc[e]    = accs * 0.25f;
            }
        }
        po[(size_t)t * STRIDE2] = make_float2(sc[0], sc[1]);
        ycur = ynext;
    }

    #pragma unroll
    for (int l = 0; l < 4; ++l)
        ((float2*)states)[(size_t)l * STRIDE2 + i2] = make_float2(av[l][0], av[l][1]);
}

// ---------------------------------------------------------------------------
// Launch
// ---------------------------------------------------------------------------
extern "C" void kernel_launch(void* const* d_in, const int* in_sizes, int n_in,
                              void* d_out, int out_size)
{
    const float* x = (const float*)d_in[0];   // [T, B, INP]
    const float* W = (const float*)d_in[1];   // [HID, INP]
    const float* b = (const float*)d_in[2];   // [HID]

    float* out    = (float*)d_out;                    // [T, B, H]
    float* states = out + (size_t)T_STEPS * BH;       // [4, B, H]

    // 1) split fp32 -> bf16 hi/mid
    const int nx4 = (int)((size_t)M_TOT * INP / 4);   // 8388608
    const int nw4 = HID * INP / 4;                    // 65536
    split_kernel<<<nx4 / 256, 256>>>((const float4*)x, nx4, 0);
    split_kernel<<<nw4 / 256, 256>>>((const float4*)W, nw4, 1);

    // 2) tensor-core projection GEMM
    cudaFuncSetAttribute(gemm_hmma_kernel,
                         cudaFuncAttributeMaxDynamicSharedMemorySize, SMEM_TOTAL);
    dim3 gemm_grid(HID / BN, M_TOT / BM);             // (4, 512)
    gemm_hmma_kernel<<<gemm_grid, 256, SMEM_TOTAL>>>(b);

    // 3) recurrent scan
    lif_scan_kernel<<<(unsigned)(BH / 2 / 256), 256>>>(out, states);
}